// round 2
// baseline (speedup 1.0000x reference)
#include <cuda_runtime.h>
#include <cstdint>

// Problem constants
#define BATCH 4
#define SEQ   2048
#define DMODEL 1024

// Scratch (device globals — no cudaMalloc allowed)
__device__ float g_Q [BATCH * SEQ * DMODEL];           // 32 MB
__device__ float g_K [BATCH * SEQ * DMODEL];           // 32 MB
__device__ float g_V [BATCH * SEQ * DMODEL];           // 32 MB
__device__ float g_P [BATCH * SEQ * SEQ];              // 64 MB (scores / probs)
__device__ float g_AO[BATCH * SEQ * DMODEL];           // 32 MB (attn output)

__device__ __forceinline__ uint32_t f2tf32(float x) {
    uint32_t r;
    asm("cvt.rna.tf32.f32 %0, %1;" : "=r"(r) : "f"(x));
    return r;
}

__device__ __forceinline__ void mma8(float c[4], const uint32_t a[4], const uint32_t b[2]) {
    asm volatile(
        "mma.sync.aligned.m16n8k8.row.col.f32.tf32.tf32.f32 "
        "{%0,%1,%2,%3}, {%4,%5,%6,%7}, {%8,%9}, {%0,%1,%2,%3};\n"
        : "+f"(c[0]), "+f"(c[1]), "+f"(c[2]), "+f"(c[3])
        : "r"(a[0]), "r"(a[1]), "r"(a[2]), "r"(a[3]), "r"(b[0]), "r"(b[1]));
}

// Generic tiled TF32 GEMM.
//   BNT = true : C = A * B^T  (A[M,K] row-major, B[N,K] row-major)  -- QK^T scores
//   BNT = false: C = A * B    (A[M,K] row-major, B[K,N] row-major)  -- projections, PV
// blockIdx.z = batch; sA/sB/sC are per-batch element strides (0 for shared operand).
// If mask != nullptr: scores epilogue (val*scale, masked -> -1e10).
// Mask layout auto-detected (int32 vs byte-bool) from a 256-byte probe.
template<bool BNT>
__global__ __launch_bounds__(256, 2)
void gemm_tf32(const float* __restrict__ A, const float* __restrict__ B,
               float* __restrict__ C, int M, int N, int K,
               size_t sA, size_t sB, size_t sC,
               const unsigned char* __restrict__ mask, float scale)
{
    constexpr int BM = 128, BN = 128, BK = 16;
    constexpr int AST = BK + 4;                       // 20 floats: conflict-free frag loads
    constexpr int BST = BNT ? (BK + 4) : (BN + 4);    // 20 (NT) or 132 (NN)

    __shared__ float As[BM * AST];
    __shared__ float Bs[BNT ? BN * (BK + 4) : BK * (BN + 4)];
    __shared__ int mask_is_int32;

    const int bz = blockIdx.z;
    A += (size_t)bz * sA;
    B += (size_t)bz * sB;
    C += (size_t)bz * sC;

    const int bm = blockIdx.y * BM;
    const int bn = blockIdx.x * BN;
    const int t    = threadIdx.x;
    const int lane = t & 31;
    const int wid  = t >> 5;
    const int wm   = wid >> 2;        // 0..1  (2 warps along M)
    const int wn   = wid & 3;         // 0..3  (4 warps along N)
    const int g    = lane >> 2;       // group id (0..7)
    const int tig  = lane & 3;        // thread-in-group (0..3)

    // Mask layout probe: if serialized as int32, every non-word-aligned byte
    // of the first 256 bytes is zero (values are only 0/1). Deterministic.
    if (mask && t == 0) {
        int is_int = 1;
        #pragma unroll 4
        for (int i = 0; i < 256; i++)
            if ((i & 3) != 0 && mask[i] != 0) is_int = 0;
        mask_is_int32 = is_int;
    }

    float acc[4][4][4];
    #pragma unroll
    for (int i = 0; i < 4; i++)
        #pragma unroll
        for (int j = 0; j < 4; j++)
            #pragma unroll
            for (int r = 0; r < 4; r++) acc[i][j][r] = 0.f;

    const int s0 = t, s1 = 256 + t;
    float4 pa0, pa1, pb0, pb1;

    // --- prefetch K-tile 0 ---
    pa0 = *(const float4*)(A + (size_t)(bm + (s0 >> 2)) * K + (s0 & 3) * 4);
    pa1 = *(const float4*)(A + (size_t)(bm + (s1 >> 2)) * K + (s1 & 3) * 4);
    if (BNT) {
        pb0 = *(const float4*)(B + (size_t)(bn + (s0 >> 2)) * K + (s0 & 3) * 4);
        pb1 = *(const float4*)(B + (size_t)(bn + (s1 >> 2)) * K + (s1 & 3) * 4);
    } else {
        pb0 = *(const float4*)(B + (size_t)(s0 >> 5) * N + bn + (s0 & 31) * 4);
        pb1 = *(const float4*)(B + (size_t)(s1 >> 5) * N + bn + (s1 & 31) * 4);
    }

    const int nkt = K / BK;
    for (int kt = 0; kt < nkt; ++kt) {
        __syncthreads();   // previous compute done before smem overwrite

        // store prefetched tiles to smem with tf32 rounding
        {
            float4 v;
            v.x = __uint_as_float(f2tf32(pa0.x)); v.y = __uint_as_float(f2tf32(pa0.y));
            v.z = __uint_as_float(f2tf32(pa0.z)); v.w = __uint_as_float(f2tf32(pa0.w));
            *(float4*)&As[(s0 >> 2) * AST + (s0 & 3) * 4] = v;
            v.x = __uint_as_float(f2tf32(pa1.x)); v.y = __uint_as_float(f2tf32(pa1.y));
            v.z = __uint_as_float(f2tf32(pa1.z)); v.w = __uint_as_float(f2tf32(pa1.w));
            *(float4*)&As[(s1 >> 2) * AST + (s1 & 3) * 4] = v;

            v.x = __uint_as_float(f2tf32(pb0.x)); v.y = __uint_as_float(f2tf32(pb0.y));
            v.z = __uint_as_float(f2tf32(pb0.z)); v.w = __uint_as_float(f2tf32(pb0.w));
            if (BNT) *(float4*)&Bs[(s0 >> 2) * BST + (s0 & 3) * 4] = v;
            else     *(float4*)&Bs[(s0 >> 5) * BST + (s0 & 31) * 4] = v;
            v.x = __uint_as_float(f2tf32(pb1.x)); v.y = __uint_as_float(f2tf32(pb1.y));
            v.z = __uint_as_float(f2tf32(pb1.z)); v.w = __uint_as_float(f2tf32(pb1.w));
            if (BNT) *(float4*)&Bs[(s1 >> 2) * BST + (s1 & 3) * 4] = v;
            else     *(float4*)&Bs[(s1 >> 5) * BST + (s1 & 31) * 4] = v;
        }
        __syncthreads();

        // prefetch next K-tile (overlaps with mma below)
        if (kt + 1 < nkt) {
            const int kk = (kt + 1) * BK;
            pa0 = *(const float4*)(A + (size_t)(bm + (s0 >> 2)) * K + kk + (s0 & 3) * 4);
            pa1 = *(const float4*)(A + (size_t)(bm + (s1 >> 2)) * K + kk + (s1 & 3) * 4);
            if (BNT) {
                pb0 = *(const float4*)(B + (size_t)(bn + (s0 >> 2)) * K + kk + (s0 & 3) * 4);
                pb1 = *(const float4*)(B + (size_t)(bn + (s1 >> 2)) * K + kk + (s1 & 3) * 4);
            } else {
                pb0 = *(const float4*)(B + (size_t)(kk + (s0 >> 5)) * N + bn + (s0 & 31) * 4);
                pb1 = *(const float4*)(B + (size_t)(kk + (s1 >> 5)) * N + bn + (s1 & 31) * 4);
            }
        }

        // compute: 2 k-steps of 8
        #pragma unroll
        for (int ks = 0; ks < 2; ++ks) {
            const int k0 = ks * 8;
            uint32_t af[4][4];
            uint32_t bf[4][2];
            #pragma unroll
            for (int i = 0; i < 4; i++) {
                const int rb = wm * 64 + i * 16;
                af[i][0] = __float_as_uint(As[(rb + g)     * AST + k0 + tig]);
                af[i][1] = __float_as_uint(As[(rb + g + 8) * AST + k0 + tig]);
                af[i][2] = __float_as_uint(As[(rb + g)     * AST + k0 + tig + 4]);
                af[i][3] = __float_as_uint(As[(rb + g + 8) * AST + k0 + tig + 4]);
            }
            #pragma unroll
            for (int j = 0; j < 4; j++) {
                const int nb = wn * 32 + j * 8;
                if (BNT) {
                    bf[j][0] = __float_as_uint(Bs[(nb + g) * BST + k0 + tig]);
                    bf[j][1] = __float_as_uint(Bs[(nb + g) * BST + k0 + tig + 4]);
                } else {
                    bf[j][0] = __float_as_uint(Bs[(k0 + tig)     * BST + nb + g]);
                    bf[j][1] = __float_as_uint(Bs[(k0 + tig + 4) * BST + nb + g]);
                }
            }
            #pragma unroll
            for (int i = 0; i < 4; i++)
                #pragma unroll
                for (int j = 0; j < 4; j++)
                    mma8(acc[i][j], af[i], bf[j]);
        }
    }

    if (mask) __syncthreads();   // make mask_is_int32 visible

    // epilogue
    #pragma unroll
    for (int i = 0; i < 4; i++) {
        const int r0 = bm + wm * 64 + i * 16 + g;
        #pragma unroll
        for (int j = 0; j < 4; j++) {
            const int c0 = bn + wn * 32 + j * 8 + tig * 2;
            float v0 = acc[i][j][0], v1 = acc[i][j][1];
            float v2 = acc[i][j][2], v3 = acc[i][j][3];
            if (mask) {
                const size_t base = (size_t)bz * M * N + (size_t)r0 * N;
                int m00, m01, m10, m11;
                if (mask_is_int32) {
                    const int* mi = (const int*)mask;
                    m00 = mi[base + c0];           m01 = mi[base + c0 + 1];
                    m10 = mi[base + 8 * N + c0];   m11 = mi[base + 8 * N + c0 + 1];
                } else {
                    m00 = mask[base + c0];         m01 = mask[base + c0 + 1];
                    m10 = mask[base + 8 * N + c0]; m11 = mask[base + 8 * N + c0 + 1];
                }
                v0 = m00 ? v0 * scale : -1e10f;
                v1 = m01 ? v1 * scale : -1e10f;
                v2 = m10 ? v2 * scale : -1e10f;
                v3 = m11 ? v3 * scale : -1e10f;
            }
            C[(size_t)r0 * N + c0]           = v0;
            C[(size_t)r0 * N + c0 + 1]       = v1;
            C[(size_t)(r0 + 8) * N + c0]     = v2;
            C[(size_t)(r0 + 8) * N + c0 + 1] = v3;
        }
    }
}

// Row softmax over width 2048; one block (256 threads) per row.
__global__ void softmax2048(float* __restrict__ P)
{
    float* p = P + (size_t)blockIdx.x * 2048;
    const int t = threadIdx.x, lane = t & 31, wid = t >> 5;
    __shared__ float red[8];

    float4 v0 = ((const float4*)p)[t];
    float4 v1 = ((const float4*)p)[t + 256];

    float m = fmaxf(fmaxf(fmaxf(v0.x, v0.y), fmaxf(v0.z, v0.w)),
                    fmaxf(fmaxf(v1.x, v1.y), fmaxf(v1.z, v1.w)));
    #pragma unroll
    for (int o = 16; o; o >>= 1) m = fmaxf(m, __shfl_xor_sync(0xffffffffu, m, o));
    if (lane == 0) red[wid] = m;
    __syncthreads();
    float bm = red[0];
    #pragma unroll
    for (int w = 1; w < 8; w++) bm = fmaxf(bm, red[w]);
    __syncthreads();

    v0.x = __expf(v0.x - bm); v0.y = __expf(v0.y - bm);
    v0.z = __expf(v0.z - bm); v0.w = __expf(v0.w - bm);
    v1.x = __expf(v1.x - bm); v1.y = __expf(v1.y - bm);
    v1.z = __expf(v1.z - bm); v1.w = __expf(v1.w - bm);

    float s = v0.x + v0.y + v0.z + v0.w + v1.x + v1.y + v1.z + v1.w;
    #pragma unroll
    for (int o = 16; o; o >>= 1) s += __shfl_xor_sync(0xffffffffu, s, o);
    if (lane == 0) red[wid] = s;
    __syncthreads();
    float bs = red[0];
    #pragma unroll
    for (int w = 1; w < 8; w++) bs += red[w];

    const float inv = 1.f / bs;
    v0.x *= inv; v0.y *= inv; v0.z *= inv; v0.w *= inv;
    v1.x *= inv; v1.y *= inv; v1.z *= inv; v1.w *= inv;
    ((float4*)p)[t]       = v0;
    ((float4*)p)[t + 256] = v1;
}

extern "C" void kernel_launch(void* const* d_in, const int* in_sizes, int n_in,
                              void* d_out, int out_size)
{
    const float*         x    = (const float*)d_in[0];
    const unsigned char* mask = (const unsigned char*)d_in[1];
    const float*         Wq   = (const float*)d_in[2];
    const float*         Wk   = (const float*)d_in[3];
    const float*         Wv   = (const float*)d_in[4];
    const float*         Wo   = (const float*)d_in[5];
    float*               out  = (float*)d_out;

    float *Q, *K, *V, *P, *AO;
    cudaGetSymbolAddress((void**)&Q,  g_Q);
    cudaGetSymbolAddress((void**)&K,  g_K);
    cudaGetSymbolAddress((void**)&V,  g_V);
    cudaGetSymbolAddress((void**)&P,  g_P);
    cudaGetSymbolAddress((void**)&AO, g_AO);

    const int MS = BATCH * SEQ;          // 8192
    dim3 blk(256);

    // QKV projections: [8192,1024] x [1024,1024]
    dim3 gp(DMODEL / 128, MS / 128, 1);
    gemm_tf32<false><<<gp, blk>>>(x, Wq, Q, MS, DMODEL, DMODEL, 0, 0, 0, nullptr, 1.f);
    gemm_tf32<false><<<gp, blk>>>(x, Wk, K, MS, DMODEL, DMODEL, 0, 0, 0, nullptr, 1.f);
    gemm_tf32<false><<<gp, blk>>>(x, Wv, V, MS, DMODEL, DMODEL, 0, 0, 0, nullptr, 1.f);

    // scores = Q K^T / 32, masked   (per batch: [2048,1024] x [2048,1024]^T)
    dim3 gs(SEQ / 128, SEQ / 128, BATCH);
    gemm_tf32<true><<<gs, blk>>>(Q, K, P, SEQ, SEQ, DMODEL,
                                 (size_t)SEQ * DMODEL, (size_t)SEQ * DMODEL,
                                 (size_t)SEQ * SEQ, mask, 0.03125f);

    // softmax over rows
    softmax2048<<<BATCH * SEQ, 256>>>(P);

    // attn_out = P V   (per batch: [2048,2048] x [2048,1024])
    dim3 gv(DMODEL / 128, SEQ / 128, BATCH);
    gemm_tf32<false><<<gv, blk>>>(P, V, AO, SEQ, DMODEL, SEQ,
                                  (size_t)SEQ * SEQ, (size_t)SEQ * DMODEL,
                                  (size_t)SEQ * DMODEL, nullptr, 1.f);

    // output projection: [8192,1024] x [1024,1024] -> d_out
    gemm_tf32<false><<<gp, blk>>>(AO, Wo, out, MS, DMODEL, DMODEL, 0, 0, 0, nullptr, 1.f);
}

// round 3
// speedup vs baseline: 1.1213x; 1.1213x over previous
#include <cuda_runtime.h>
#include <cstdint>

// Problem constants
#define BATCH 4
#define SEQ   2048
#define DMODEL 1024

// Scratch (device globals — no cudaMalloc allowed)
__device__ float g_QKV[(size_t)3 * BATCH * SEQ * DMODEL];   // 96 MB (Q,K,V)
__device__ float g_P  [(size_t)BATCH * SEQ * SEQ];          // 64 MB (scores/probs)
__device__ float g_AO [(size_t)BATCH * SEQ * DMODEL];       // 32 MB

__device__ __forceinline__ uint32_t f2tf32(float x) {
    uint32_t r;
    asm("cvt.rna.tf32.f32 %0, %1;" : "=r"(r) : "f"(x));
    return r;
}

__device__ __forceinline__ void mma8(float c[4], const uint32_t a[4], const uint32_t b[2]) {
    asm volatile(
        "mma.sync.aligned.m16n8k8.row.col.f32.tf32.tf32.f32 "
        "{%0,%1,%2,%3}, {%4,%5,%6,%7}, {%8,%9}, {%0,%1,%2,%3};\n"
        : "+f"(c[0]), "+f"(c[1]), "+f"(c[2]), "+f"(c[3])
        : "r"(a[0]), "r"(a[1]), "r"(a[2]), "r"(a[3]), "r"(b[0]), "r"(b[1]));
}

__device__ __forceinline__ void cpa16(float* dst, const float* src) {
    uint32_t d = (uint32_t)__cvta_generic_to_shared(dst);
    asm volatile("cp.async.cg.shared.global [%0], [%1], 16;\n" :: "r"(d), "l"(src));
}

// Tiled TF32 GEMM, 4-stage cp.async pipeline.
//   BNT = true : C = A * B^T   (A[M,K], B[N,K] row-major)  -- QK^T scores
//   BNT = false: C = A * B     (A[M,K], B[K,N] row-major)  -- projections, PV
//   TRIPLE     : blockIdx.z selects B among {B0,B1,B2}, C += z*sC (QKV fusion)
// If mask != nullptr: epilogue val*scale, masked -> -1e10 (layout auto-probe).
template<bool BNT, bool TRIPLE>
__global__ __launch_bounds__(256, 2)
void gemm_tf32(const float* __restrict__ A, const float* __restrict__ B0,
               const float* __restrict__ B1, const float* __restrict__ B2,
               float* __restrict__ C, int M, int N, int K,
               size_t sA, size_t sB, size_t sC,
               const unsigned char* __restrict__ mask, float scale)
{
    constexpr int BM = 128, BN = 128, BK = 16;
    constexpr int AST = 20;                    // A smem row stride (floats)
    constexpr int BST = BNT ? 20 : 132;        // B smem row stride
    constexpr int ASZ = BM * AST;              // 2560 floats
    constexpr int BSZ = BNT ? BN * 20 : BK * 132;
    constexpr int STG = ASZ + BSZ;
    constexpr int NSTAGE = 4;

    extern __shared__ float sm[];
    __shared__ int mask_is_int32;

    const int bz = blockIdx.z;
    const float* B;
    if (TRIPLE) {
        B = (bz == 0) ? B0 : (bz == 1 ? B1 : B2);
        C += (size_t)bz * sC;
    } else {
        B = B0;
        A += (size_t)bz * sA;
        B += (size_t)bz * sB;
        C += (size_t)bz * sC;
    }

    const int bm = blockIdx.y * BM;
    const int bn = blockIdx.x * BN;
    const int t    = threadIdx.x;
    const int lane = t & 31;
    const int wid  = t >> 5;
    const int wm   = wid >> 2;        // 0..1
    const int wn   = wid & 3;         // 0..3
    const int g    = lane >> 2;       // 0..7
    const int tig  = lane & 3;        // 0..3

    // Mask layout probe (int32 vs byte-bool). Deterministic for 0/1 data.
    if (mask && t == 0) {
        int is_int = 1;
        #pragma unroll 4
        for (int i = 0; i < 256; i++)
            if ((i & 3) != 0 && mask[i] != 0) is_int = 0;
        mask_is_int32 = is_int;
    }

    float acc[4][4][4];
    #pragma unroll
    for (int i = 0; i < 4; i++)
        #pragma unroll
        for (int j = 0; j < 4; j++)
            #pragma unroll
            for (int r = 0; r < 4; r++) acc[i][j][r] = 0.f;

    const int nkt = K / BK;

    auto issue = [&](int kt) {
        float* As = sm + (kt % NSTAGE) * STG;
        float* Bs = As + ASZ;
        const int kk = kt * BK;
        #pragma unroll
        for (int h = 0; h < 2; h++) {
            const int s = h * 256 + t;
            const int r = s >> 2, c = s & 3;
            cpa16(&As[r * AST + c * 4], A + (size_t)(bm + r) * K + kk + c * 4);
            if (BNT) {
                cpa16(&Bs[r * BST + c * 4], B + (size_t)(bn + r) * K + kk + c * 4);
            } else {
                const int kr = s >> 5, cc = s & 31;
                cpa16(&Bs[kr * BST + cc * 4], B + (size_t)(kk + kr) * N + bn + cc * 4);
            }
        }
        asm volatile("cp.async.commit_group;\n");
    };

    // prologue: 3 stages in flight
    issue(0); issue(1); issue(2);

    for (int kt = 0; kt < nkt; ++kt) {
        const int nw = nkt - 1 - kt;  // groups allowed to remain pending
        if (nw >= 2)      asm volatile("cp.async.wait_group 2;\n");
        else if (nw == 1) asm volatile("cp.async.wait_group 1;\n");
        else              asm volatile("cp.async.wait_group 0;\n");
        __syncthreads();

        if (kt + 3 < nkt) issue(kt + 3);

        const float* As = sm + (kt % NSTAGE) * STG;
        const float* Bs = As + ASZ;

        #pragma unroll
        for (int ks = 0; ks < 2; ++ks) {
            const int k0 = ks * 8;
            uint32_t af[4][4];
            uint32_t bf[4][2];
            #pragma unroll
            for (int i = 0; i < 4; i++) {
                const int rb = wm * 64 + i * 16;
                af[i][0] = f2tf32(As[(rb + g)     * AST + k0 + tig]);
                af[i][1] = f2tf32(As[(rb + g + 8) * AST + k0 + tig]);
                af[i][2] = f2tf32(As[(rb + g)     * AST + k0 + tig + 4]);
                af[i][3] = f2tf32(As[(rb + g + 8) * AST + k0 + tig + 4]);
            }
            #pragma unroll
            for (int j = 0; j < 4; j++) {
                const int nb = wn * 32 + j * 8;
                if (BNT) {
                    bf[j][0] = f2tf32(Bs[(nb + g) * BST + k0 + tig]);
                    bf[j][1] = f2tf32(Bs[(nb + g) * BST + k0 + tig + 4]);
                } else {
                    bf[j][0] = f2tf32(Bs[(k0 + tig)     * BST + nb + g]);
                    bf[j][1] = f2tf32(Bs[(k0 + tig + 4) * BST + nb + g]);
                }
            }
            #pragma unroll
            for (int i = 0; i < 4; i++)
                #pragma unroll
                for (int j = 0; j < 4; j++)
                    mma8(acc[i][j], af[i], bf[j]);
        }
    }

    // epilogue
    #pragma unroll
    for (int i = 0; i < 4; i++) {
        const int r0 = bm + wm * 64 + i * 16 + g;
        #pragma unroll
        for (int j = 0; j < 4; j++) {
            const int c0 = bn + wn * 32 + j * 8 + tig * 2;
            float v0 = acc[i][j][0], v1 = acc[i][j][1];
            float v2 = acc[i][j][2], v3 = acc[i][j][3];
            if (mask) {
                const size_t base = (size_t)bz * M * N + (size_t)r0 * N;
                int m00, m01, m10, m11;
                if (mask_is_int32) {
                    const int* mi = (const int*)mask;
                    int2 ma = *(const int2*)&mi[base + c0];
                    int2 mb = *(const int2*)&mi[base + (size_t)8 * N + c0];
                    m00 = ma.x; m01 = ma.y; m10 = mb.x; m11 = mb.y;
                } else {
                    m00 = mask[base + c0];                   m01 = mask[base + c0 + 1];
                    m10 = mask[base + (size_t)8 * N + c0];   m11 = mask[base + (size_t)8 * N + c0 + 1];
                }
                v0 = m00 ? v0 * scale : -1e10f;
                v1 = m01 ? v1 * scale : -1e10f;
                v2 = m10 ? v2 * scale : -1e10f;
                v3 = m11 ? v3 * scale : -1e10f;
            }
            float2 w0 = {v0, v1}, w1 = {v2, v3};
            *(float2*)&C[(size_t)r0 * N + c0]       = w0;
            *(float2*)&C[(size_t)(r0 + 8) * N + c0] = w1;
        }
    }
}

// Row softmax over width 2048; one block (256 threads) per row.
__global__ void softmax2048(float* __restrict__ P)
{
    float* p = P + (size_t)blockIdx.x * 2048;
    const int t = threadIdx.x, lane = t & 31, wid = t >> 5;
    __shared__ float red[8];

    float4 v0 = ((const float4*)p)[t];
    float4 v1 = ((const float4*)p)[t + 256];

    float m = fmaxf(fmaxf(fmaxf(v0.x, v0.y), fmaxf(v0.z, v0.w)),
                    fmaxf(fmaxf(v1.x, v1.y), fmaxf(v1.z, v1.w)));
    #pragma unroll
    for (int o = 16; o; o >>= 1) m = fmaxf(m, __shfl_xor_sync(0xffffffffu, m, o));
    if (lane == 0) red[wid] = m;
    __syncthreads();
    float bm = red[0];
    #pragma unroll
    for (int w = 1; w < 8; w++) bm = fmaxf(bm, red[w]);
    __syncthreads();

    v0.x = __expf(v0.x - bm); v0.y = __expf(v0.y - bm);
    v0.z = __expf(v0.z - bm); v0.w = __expf(v0.w - bm);
    v1.x = __expf(v1.x - bm); v1.y = __expf(v1.y - bm);
    v1.z = __expf(v1.z - bm); v1.w = __expf(v1.w - bm);

    float s = v0.x + v0.y + v0.z + v0.w + v1.x + v1.y + v1.z + v1.w;
    #pragma unroll
    for (int o = 16; o; o >>= 1) s += __shfl_xor_sync(0xffffffffu, s, o);
    if (lane == 0) red[wid] = s;
    __syncthreads();
    float bs = red[0];
    #pragma unroll
    for (int w = 1; w < 8; w++) bs += red[w];

    const float inv = 1.f / bs;
    v0.x *= inv; v0.y *= inv; v0.z *= inv; v0.w *= inv;
    v1.x *= inv; v1.y *= inv; v1.z *= inv; v1.w *= inv;
    ((float4*)p)[t]       = v0;
    ((float4*)p)[t + 256] = v1;
}

extern "C" void kernel_launch(void* const* d_in, const int* in_sizes, int n_in,
                              void* d_out, int out_size)
{
    const float*         x    = (const float*)d_in[0];
    const unsigned char* mask = (const unsigned char*)d_in[1];
    const float*         Wq   = (const float*)d_in[2];
    const float*         Wk   = (const float*)d_in[3];
    const float*         Wv   = (const float*)d_in[4];
    const float*         Wo   = (const float*)d_in[5];
    float*               out  = (float*)d_out;

    float *QKV, *P, *AO;
    cudaGetSymbolAddress((void**)&QKV, g_QKV);
    cudaGetSymbolAddress((void**)&P,   g_P);
    cudaGetSymbolAddress((void**)&AO,  g_AO);

    const size_t pstride = (size_t)BATCH * SEQ * DMODEL;   // Q/K/V plane stride
    float* Q = QKV;
    float* K = QKV + pstride;
    float* V = QKV + 2 * pstride;

    // dynamic smem sizes (floats -> bytes), 4 stages
    const int smemNN = (2560 + 16 * 132) * 4 * 4;   // 74752
    const int smemNT = (2560 + 2560)     * 4 * 4;   // 81920

    cudaFuncSetAttribute(gemm_tf32<false, true>,
                         cudaFuncAttributeMaxDynamicSharedMemorySize, smemNN);
    cudaFuncSetAttribute(gemm_tf32<false, false>,
                         cudaFuncAttributeMaxDynamicSharedMemorySize, smemNN);
    cudaFuncSetAttribute(gemm_tf32<true, false>,
                         cudaFuncAttributeMaxDynamicSharedMemorySize, smemNT);

    const int MS = BATCH * SEQ;          // 8192
    dim3 blk(256);

    // QKV projections fused: z selects W; [8192,1024] x [1024,1024]
    dim3 gqkv(DMODEL / 128, MS / 128, 3);
    gemm_tf32<false, true><<<gqkv, blk, smemNN>>>(
        x, Wq, Wk, Wv, QKV, MS, DMODEL, DMODEL, 0, 0, pstride, nullptr, 1.f);

    // scores = Q K^T / 32, masked   (per batch: [2048,1024] x [2048,1024]^T)
    dim3 gs(SEQ / 128, SEQ / 128, BATCH);
    gemm_tf32<true, false><<<gs, blk, smemNT>>>(
        Q, K, nullptr, nullptr, P, SEQ, SEQ, DMODEL,
        (size_t)SEQ * DMODEL, (size_t)SEQ * DMODEL, (size_t)SEQ * SEQ,
        mask, 0.03125f);

    // softmax over rows
    softmax2048<<<BATCH * SEQ, 256>>>(P);

    // attn_out = P V   (per batch: [2048,2048] x [2048,1024])
    dim3 gv(DMODEL / 128, SEQ / 128, BATCH);
    gemm_tf32<false, false><<<gv, blk, smemNN>>>(
        P, V, nullptr, nullptr, AO, SEQ, DMODEL, SEQ,
        (size_t)SEQ * SEQ, (size_t)SEQ * DMODEL, (size_t)SEQ * DMODEL,
        nullptr, 1.f);

    // output projection: [8192,1024] x [1024,1024] -> d_out
    dim3 gp(DMODEL / 128, MS / 128, 1);
    gemm_tf32<false, false><<<gp, blk, smemNN>>>(
        AO, Wo, nullptr, nullptr, out, MS, DMODEL, DMODEL, 0, 0, 0, nullptr, 1.f);
}

// round 4
// speedup vs baseline: 1.2146x; 1.0832x over previous
#include <cuda_runtime.h>
#include <cstdint>

#define BATCH 4
#define SEQ   2048
#define DMODEL 1024

// Scratch (device globals — no cudaMalloc allowed)
__device__ float g_QKV[(size_t)3 * BATCH * SEQ * DMODEL];   // 96 MB (Q,K,V)
__device__ float g_P  [(size_t)BATCH * SEQ * SEQ];          // 64 MB (scores/probs)
__device__ float g_AO [(size_t)BATCH * SEQ * DMODEL];       // 32 MB
__device__ float g_X  [(size_t)BATCH * SEQ * DMODEL];       // 32 MB (tf32-rounded x)
__device__ float g_W  [(size_t)4 * DMODEL * DMODEL];        // 16 MB (rounded Wq,Wk,Wv,Wo)

__device__ __forceinline__ uint32_t f2tf32(float x) {
    uint32_t r;
    asm("cvt.rna.tf32.f32 %0, %1;" : "=r"(r) : "f"(x));
    return r;
}
__device__ __forceinline__ float rtf(float x) { return __uint_as_float(f2tf32(x)); }

__device__ __forceinline__ void mma8(float c[4], const uint32_t a[4], const uint32_t b[2]) {
    asm volatile(
        "mma.sync.aligned.m16n8k8.row.col.f32.tf32.tf32.f32 "
        "{%0,%1,%2,%3}, {%4,%5,%6,%7}, {%8,%9}, {%0,%1,%2,%3};\n"
        : "+f"(c[0]), "+f"(c[1]), "+f"(c[2]), "+f"(c[3])
        : "r"(a[0]), "r"(a[1]), "r"(a[2]), "r"(a[3]), "r"(b[0]), "r"(b[1]));
}

__device__ __forceinline__ void cpa16(float* dst, const float* src) {
    uint32_t d = (uint32_t)__cvta_generic_to_shared(dst);
    asm volatile("cp.async.cg.shared.global [%0], [%1], 16;\n" :: "r"(d), "l"(src));
}

// ldmatrix x4 over b16-typed tiles: for fp32/tf32 data each 8x8 b16 tile is an
// 8-row x 4-float tile; lane t receives row t/4, float-column t%4 as one .b32.
__device__ __forceinline__ void ldmx4(uint32_t r[4], const float* p) {
    uint32_t a = (uint32_t)__cvta_generic_to_shared(p);
    asm volatile("ldmatrix.sync.aligned.m8n8.x4.shared.b16 {%0,%1,%2,%3}, [%4];"
        : "=r"(r[0]), "=r"(r[1]), "=r"(r[2]), "=r"(r[3]) : "r"(a));
}

// Elementwise tf32 rounding (inputs pre-pass).
__global__ void round_tf32(const float4* __restrict__ in, float4* __restrict__ out, int n4)
{
    int i = blockIdx.x * blockDim.x + threadIdx.x;
    if (i < n4) {
        float4 v = in[i];
        v.x = rtf(v.x); v.y = rtf(v.y); v.z = rtf(v.z); v.w = rtf(v.w);
        out[i] = v;
    }
}

// Tiled TF32 GEMM, 4-stage cp.async pipeline, ldmatrix fragment loads.
// All inputs are assumed already tf32-rounded (no cvt in mainloop).
//   BNT = true : C = A * B^T   (A[M,K], B[N,K] row-major)  -- QK^T scores
//   BNT = false: C = A * B     (A[M,K], B[K,N] row-major)  -- projections, PV
//   TRIPLE     : blockIdx.z selects B among {B0,B1,B2}, C += z*sC (QKV fusion)
// roundC: round outputs to tf32 (when C feeds a later GEMM).
// mask: epilogue val*scale, masked -> -1e10 (layout auto-probe int32 vs byte).
template<bool BNT, bool TRIPLE>
__global__ __launch_bounds__(256, 2)
void gemm_tf32(const float* __restrict__ A, const float* __restrict__ B0,
               const float* __restrict__ B1, const float* __restrict__ B2,
               float* __restrict__ C, int M, int N, int K,
               size_t sA, size_t sB, size_t sC,
               const unsigned char* __restrict__ mask, float scale, int roundC)
{
    constexpr int BM = 128, BN = 128, BK = 16;
    constexpr int AST = 20;                    // A smem row stride (floats)
    constexpr int BST = BNT ? 20 : 132;        // B smem row stride
    constexpr int ASZ = BM * AST;              // 2560 floats
    constexpr int BSZ = BNT ? BN * 20 : BK * 132;
    constexpr int STG = ASZ + BSZ;
    constexpr int NSTAGE = 4;

    extern __shared__ float sm[];
    __shared__ int mask_is_int32;

    const int bz = blockIdx.z;
    const float* B;
    if (TRIPLE) {
        B = (bz == 0) ? B0 : (bz == 1 ? B1 : B2);
        C += (size_t)bz * sC;
    } else {
        B = B0;
        A += (size_t)bz * sA;
        B += (size_t)bz * sB;
        C += (size_t)bz * sC;
    }

    const int bm = blockIdx.y * BM;
    const int bn = blockIdx.x * BN;
    const int t    = threadIdx.x;
    const int lane = t & 31;
    const int wid  = t >> 5;
    const int wm   = wid >> 2;        // 0..1
    const int wn   = wid & 3;         // 0..3
    const int g    = lane >> 2;       // 0..7
    const int tig  = lane & 3;        // 0..3

    if (mask && t == 0) {
        int is_int = 1;
        #pragma unroll 4
        for (int i = 0; i < 256; i++)
            if ((i & 3) != 0 && mask[i] != 0) is_int = 0;
        mask_is_int32 = is_int;
    }

    float acc[4][4][4];
    #pragma unroll
    for (int i = 0; i < 4; i++)
        #pragma unroll
        for (int j = 0; j < 4; j++)
            #pragma unroll
            for (int r = 0; r < 4; r++) acc[i][j][r] = 0.f;

    const int nkt = K / BK;

    auto issue = [&](int kt) {
        float* As = sm + (kt % NSTAGE) * STG;
        float* Bs = As + ASZ;
        const int kk = kt * BK;
        #pragma unroll
        for (int h = 0; h < 2; h++) {
            const int s = h * 256 + t;
            const int r = s >> 2, c = s & 3;
            cpa16(&As[r * AST + c * 4], A + (size_t)(bm + r) * K + kk + c * 4);
            if (BNT) {
                cpa16(&Bs[r * BST + c * 4], B + (size_t)(bn + r) * K + kk + c * 4);
            } else {
                const int kr = s >> 5, cc = s & 31;
                cpa16(&Bs[kr * BST + cc * 4], B + (size_t)(kk + kr) * N + bn + cc * 4);
            }
        }
        asm volatile("cp.async.commit_group;\n");
    };

    issue(0); issue(1); issue(2);

    // ldmatrix per-lane row/col selectors (constant across k-loop)
    const int a_row = (lane & 15);            // row within 16-row tile group
    const int a_kof = (lane >> 4) << 2;       // 0 or 4
    const int b_row = (lane & 7) + ((lane & 16) >> 1);   // NT: row within 16-n group
    const int b_kof = (lane & 8) >> 1;                   // 0 or 4

    for (int kt = 0; kt < nkt; ++kt) {
        const int nw = nkt - 1 - kt;
        if (nw >= 2)      asm volatile("cp.async.wait_group 2;\n");
        else if (nw == 1) asm volatile("cp.async.wait_group 1;\n");
        else              asm volatile("cp.async.wait_group 0;\n");
        __syncthreads();

        if (kt + 3 < nkt) issue(kt + 3);

        const float* As = sm + (kt % NSTAGE) * STG;
        const float* Bs = As + ASZ;

        #pragma unroll
        for (int ks = 0; ks < 2; ++ks) {
            const int k0 = ks * 8;
            uint32_t af[4][4];
            uint32_t bf[4][2];
            #pragma unroll
            for (int i = 0; i < 4; i++) {
                const int rb = wm * 64 + i * 16;
                ldmx4(af[i], &As[(rb + a_row) * AST + k0 + a_kof]);
            }
            if (BNT) {
                #pragma unroll
                for (int jp = 0; jp < 2; jp++) {
                    uint32_t bq[4];
                    const int nb = wn * 32 + jp * 16;
                    ldmx4(bq, &Bs[(nb + b_row) * BST + k0 + b_kof]);
                    bf[jp * 2][0]     = bq[0];
                    bf[jp * 2][1]     = bq[1];
                    bf[jp * 2 + 1][0] = bq[2];
                    bf[jp * 2 + 1][1] = bq[3];
                }
            } else {
                #pragma unroll
                for (int j = 0; j < 4; j++) {
                    const int nb = wn * 32 + j * 8;
                    bf[j][0] = __float_as_uint(Bs[(k0 + tig)     * BST + nb + g]);
                    bf[j][1] = __float_as_uint(Bs[(k0 + tig + 4) * BST + nb + g]);
                }
            }
            #pragma unroll
            for (int i = 0; i < 4; i++)
                #pragma unroll
                for (int j = 0; j < 4; j++)
                    mma8(acc[i][j], af[i], bf[j]);
        }
    }

    if (mask) __syncthreads();   // make mask_is_int32 visible

    #pragma unroll
    for (int i = 0; i < 4; i++) {
        const int r0 = bm + wm * 64 + i * 16 + g;
        #pragma unroll
        for (int j = 0; j < 4; j++) {
            const int c0 = bn + wn * 32 + j * 8 + tig * 2;
            float v0 = acc[i][j][0], v1 = acc[i][j][1];
            float v2 = acc[i][j][2], v3 = acc[i][j][3];
            if (mask) {
                const size_t base = (size_t)bz * M * N + (size_t)r0 * N;
                int m00, m01, m10, m11;
                if (mask_is_int32) {
                    const int* mi = (const int*)mask;
                    int2 ma = *(const int2*)&mi[base + c0];
                    int2 mb = *(const int2*)&mi[base + (size_t)8 * N + c0];
                    m00 = ma.x; m01 = ma.y; m10 = mb.x; m11 = mb.y;
                } else {
                    m00 = mask[base + c0];                   m01 = mask[base + c0 + 1];
                    m10 = mask[base + (size_t)8 * N + c0];   m11 = mask[base + (size_t)8 * N + c0 + 1];
                }
                v0 = m00 ? v0 * scale : -1e10f;
                v1 = m01 ? v1 * scale : -1e10f;
                v2 = m10 ? v2 * scale : -1e10f;
                v3 = m11 ? v3 * scale : -1e10f;
            }
            if (roundC) {
                v0 = rtf(v0); v1 = rtf(v1); v2 = rtf(v2); v3 = rtf(v3);
            }
            float2 w0 = {v0, v1}, w1 = {v2, v3};
            *(float2*)&C[(size_t)r0 * N + c0]       = w0;
            *(float2*)&C[(size_t)(r0 + 8) * N + c0] = w1;
        }
    }
}

// Row softmax over width 2048; one block (256 threads) per row.
// Output rounded to tf32 (feeds PV GEMM).
__global__ void softmax2048(float* __restrict__ P)
{
    float* p = P + (size_t)blockIdx.x * 2048;
    const int t = threadIdx.x, lane = t & 31, wid = t >> 5;
    __shared__ float red[8];

    float4 v0 = ((const float4*)p)[t];
    float4 v1 = ((const float4*)p)[t + 256];

    float m = fmaxf(fmaxf(fmaxf(v0.x, v0.y), fmaxf(v0.z, v0.w)),
                    fmaxf(fmaxf(v1.x, v1.y), fmaxf(v1.z, v1.w)));
    #pragma unroll
    for (int o = 16; o; o >>= 1) m = fmaxf(m, __shfl_xor_sync(0xffffffffu, m, o));
    if (lane == 0) red[wid] = m;
    __syncthreads();
    float bm = red[0];
    #pragma unroll
    for (int w = 1; w < 8; w++) bm = fmaxf(bm, red[w]);
    __syncthreads();

    v0.x = __expf(v0.x - bm); v0.y = __expf(v0.y - bm);
    v0.z = __expf(v0.z - bm); v0.w = __expf(v0.w - bm);
    v1.x = __expf(v1.x - bm); v1.y = __expf(v1.y - bm);
    v1.z = __expf(v1.z - bm); v1.w = __expf(v1.w - bm);

    float s = v0.x + v0.y + v0.z + v0.w + v1.x + v1.y + v1.z + v1.w;
    #pragma unroll
    for (int o = 16; o; o >>= 1) s += __shfl_xor_sync(0xffffffffu, s, o);
    if (lane == 0) red[wid] = s;
    __syncthreads();
    float bs = red[0];
    #pragma unroll
    for (int w = 1; w < 8; w++) bs += red[w];

    const float inv = 1.f / bs;
    v0.x = rtf(v0.x * inv); v0.y = rtf(v0.y * inv);
    v0.z = rtf(v0.z * inv); v0.w = rtf(v0.w * inv);
    v1.x = rtf(v1.x * inv); v1.y = rtf(v1.y * inv);
    v1.z = rtf(v1.z * inv); v1.w = rtf(v1.w * inv);
    ((float4*)p)[t]       = v0;
    ((float4*)p)[t + 256] = v1;
}

extern "C" void kernel_launch(void* const* d_in, const int* in_sizes, int n_in,
                              void* d_out, int out_size)
{
    const float*         x    = (const float*)d_in[0];
    const unsigned char* mask = (const unsigned char*)d_in[1];
    const float*         Wq   = (const float*)d_in[2];
    const float*         Wk   = (const float*)d_in[3];
    const float*         Wv   = (const float*)d_in[4];
    const float*         Wo   = (const float*)d_in[5];
    float*               out  = (float*)d_out;

    float *QKV, *P, *AO, *X, *W;
    cudaGetSymbolAddress((void**)&QKV, g_QKV);
    cudaGetSymbolAddress((void**)&P,   g_P);
    cudaGetSymbolAddress((void**)&AO,  g_AO);
    cudaGetSymbolAddress((void**)&X,   g_X);
    cudaGetSymbolAddress((void**)&W,   g_W);

    const size_t pstride = (size_t)BATCH * SEQ * DMODEL;   // Q/K/V plane stride
    const size_t wsz = (size_t)DMODEL * DMODEL;            // 1M elems
    float* rWq = W;
    float* rWk = W + wsz;
    float* rWv = W + 2 * wsz;
    float* rWo = W + 3 * wsz;
    float* Q = QKV;
    float* K = QKV + pstride;
    float* V = QKV + 2 * pstride;

    // --- pre-round inputs to tf32 ---
    {
        const int xe4 = (int)(pstride / 4);
        round_tf32<<<(xe4 + 255) / 256, 256>>>((const float4*)x, (float4*)X, xe4);
        const int we4 = (int)(wsz / 4);
        round_tf32<<<(we4 + 255) / 256, 256>>>((const float4*)Wq, (float4*)rWq, we4);
        round_tf32<<<(we4 + 255) / 256, 256>>>((const float4*)Wk, (float4*)rWk, we4);
        round_tf32<<<(we4 + 255) / 256, 256>>>((const float4*)Wv, (float4*)rWv, we4);
        round_tf32<<<(we4 + 255) / 256, 256>>>((const float4*)Wo, (float4*)rWo, we4);
    }

    const int smemNN = (2560 + 16 * 132) * 4 * 4;   // 74752 B
    const int smemNT = (2560 + 2560)     * 4 * 4;   // 81920 B

    cudaFuncSetAttribute(gemm_tf32<false, true>,
                         cudaFuncAttributeMaxDynamicSharedMemorySize, smemNN);
    cudaFuncSetAttribute(gemm_tf32<false, false>,
                         cudaFuncAttributeMaxDynamicSharedMemorySize, smemNN);
    cudaFuncSetAttribute(gemm_tf32<true, false>,
                         cudaFuncAttributeMaxDynamicSharedMemorySize, smemNT);

    const int MS = BATCH * SEQ;          // 8192
    dim3 blk(256);

    // QKV projections fused: z selects W; [8192,1024] x [1024,1024]; round outputs
    dim3 gqkv(DMODEL / 128, MS / 128, 3);
    gemm_tf32<false, true><<<gqkv, blk, smemNN>>>(
        X, rWq, rWk, rWv, QKV, MS, DMODEL, DMODEL, 0, 0, pstride, nullptr, 1.f, 1);

    // scores = Q K^T / 32, masked (softmax rounds its own output)
    dim3 gs(SEQ / 128, SEQ / 128, BATCH);
    gemm_tf32<true, false><<<gs, blk, smemNT>>>(
        Q, K, nullptr, nullptr, P, SEQ, SEQ, DMODEL,
        (size_t)SEQ * DMODEL, (size_t)SEQ * DMODEL, (size_t)SEQ * SEQ,
        mask, 0.03125f, 0);

    softmax2048<<<BATCH * SEQ, 256>>>(P);

    // attn_out = P V; round outputs (feeds out-proj)
    dim3 gv(DMODEL / 128, SEQ / 128, BATCH);
    gemm_tf32<false, false><<<gv, blk, smemNN>>>(
        P, V, nullptr, nullptr, AO, SEQ, DMODEL, SEQ,
        (size_t)SEQ * SEQ, (size_t)SEQ * DMODEL, (size_t)SEQ * DMODEL,
        nullptr, 1.f, 1);

    // output projection -> d_out (no rounding)
    dim3 gp(DMODEL / 128, MS / 128, 1);
    gemm_tf32<false, false><<<gp, blk, smemNN>>>(
        AO, rWo, nullptr, nullptr, out, MS, DMODEL, DMODEL, 0, 0, 0, nullptr, 1.f, 0);
}